// round 10
// baseline (speedup 1.0000x reference)
#include <cuda_runtime.h>
#include <math.h>

#define N_NODES 100000
#define N_EDGES 3200000
#define K_IN    1433
#define C1      16

// ---------------- scratch (static device globals; no allocation) ------------
__device__ __align__(16) int   g_cnt[N_NODES];
__device__ __align__(16) int   g_off[N_NODES + 4];
__device__ __align__(16) int   g_pos[N_NODES];
__device__ __align__(16) float g_dinv[N_NODES];
__device__ __align__(16) int   g_ecol[N_EDGES];
__device__ __align__(16) float g_h1[N_NODES * 16];
__device__ __align__(16) float g_h2[N_NODES * 8];

// ---------------- degree / CSR build ---------------------------------------
__global__ void k_zero_cnt() {
    int i = blockIdx.x * blockDim.x + threadIdx.x;
    if (i * 4 < N_NODES) ((int4*)g_cnt)[i] = make_int4(0, 0, 0, 0);
}

__global__ void k_count(const int* __restrict__ row) {
    int i = blockIdx.x * blockDim.x + threadIdx.x;     // 8 edges per thread
    if (i * 8 >= N_EDGES) return;
    int4 r0 = ((const int4*)row)[2 * i];
    int4 r1 = ((const int4*)row)[2 * i + 1];
    atomicAdd(&g_cnt[r0.x], 1);
    atomicAdd(&g_cnt[r0.y], 1);
    atomicAdd(&g_cnt[r0.z], 1);
    atomicAdd(&g_cnt[r0.w], 1);
    atomicAdd(&g_cnt[r1.x], 1);
    atomicAdd(&g_cnt[r1.y], 1);
    atomicAdd(&g_cnt[r1.z], 1);
    atomicAdd(&g_cnt[r1.w], 1);
}

// single-block exclusive scan of counts -> offsets; also dinv = rsqrt(deg+1)
__global__ void k_scan() {
    const int T = 1024, ACT = 1000, CH4 = 25;          // 1000*100 = 100000
    int t = threadIdx.x;
    __shared__ int ps[T];
    int sum = 0;
    if (t < ACT) {
        const int4* c4 = (const int4*)g_cnt + t * CH4;
#pragma unroll
        for (int i = 0; i < CH4; i++) { int4 v = c4[i]; sum += v.x + v.y + v.z + v.w; }
    }
    ps[t] = sum;
    __syncthreads();
    for (int off = 1; off < T; off <<= 1) {
        int v = (t >= off) ? ps[t - off] : 0;
        __syncthreads();
        ps[t] += v;
        __syncthreads();
    }
    if (t < ACT) {
        int run = (t > 0) ? ps[t - 1] : 0;
        const int4* c4 = (const int4*)g_cnt + t * CH4;
        int4*   o4 = (int4*)g_off + t * CH4;
        int4*   p4 = (int4*)g_pos + t * CH4;
        float4* d4 = (float4*)g_dinv + t * CH4;
#pragma unroll 5
        for (int i = 0; i < CH4; i++) {
            int4 v = c4[i];
            int4 o;
            o.x = run; o.y = o.x + v.x; o.z = o.y + v.y; o.w = o.z + v.z;
            run = o.w + v.w;
            o4[i] = o; p4[i] = o;
            float4 dv;
            dv.x = rsqrtf((float)(v.x + 1)); dv.y = rsqrtf((float)(v.y + 1));
            dv.z = rsqrtf((float)(v.z + 1)); dv.w = rsqrtf((float)(v.w + 1));
            d4[i] = dv;
        }
        if (t == ACT - 1) g_off[N_NODES] = run;
    }
}

__global__ void k_place(const int* __restrict__ row, const int* __restrict__ col) {
    int i = blockIdx.x * blockDim.x + threadIdx.x;     // 8 edges per thread
    if (i * 8 >= N_EDGES) return;
    int4 r0 = ((const int4*)row)[2 * i];
    int4 r1 = ((const int4*)row)[2 * i + 1];
    int4 c0 = ((const int4*)col)[2 * i];
    int4 c1 = ((const int4*)col)[2 * i + 1];
    int p0 = atomicAdd(&g_pos[r0.x], 1);
    int p1 = atomicAdd(&g_pos[r0.y], 1);
    int p2 = atomicAdd(&g_pos[r0.z], 1);
    int p3 = atomicAdd(&g_pos[r0.w], 1);
    int p4 = atomicAdd(&g_pos[r1.x], 1);
    int p5 = atomicAdd(&g_pos[r1.y], 1);
    int p6 = atomicAdd(&g_pos[r1.z], 1);
    int p7 = atomicAdd(&g_pos[r1.w], 1);
    g_ecol[p0] = c0.x;
    g_ecol[p1] = c0.y;
    g_ecol[p2] = c0.z;
    g_ecol[p3] = c0.w;
    g_ecol[p4] = c1.x;
    g_ecol[p5] = c1.y;
    g_ecol[p6] = c1.z;
    g_ecol[p7] = c1.w;
}

// ---------------- GEMM1: h1 = x @ W1, 16B-aligned cp.async -------------------
// Row m's k-window [8t, 8t+8) starts at global float F = m*1433 + 8t with
// F mod 4 = m mod 4 (constant in t). Copy three 16B chunks [F-o, F-o+12)
// per row per tile (o = m&3); compute reads at per-lane offset (lm&3).
#define G1_BLOCK 256
#define G1_MT    768            // 3 * 256, zero masked-lane waste
#define G1_GRID  131            // ceil(100000/768)
#define G1_NT    179            // full 8-wide k tiles (k 0..1431); k=1432 epilogue
#define SROW     12             // floats per row slot (3 x 16B chunks)
#define STAGE_F  (G1_MT * SROW) // 9216 floats; max read 767*12+3+7 = 9214 OK
#define STAGES   3
#define WS_FLOATS (K_IN * C1)   // 22928
#define G1_SMEM_FLOATS (WS_FLOATS + STAGES * STAGE_F)   // 50576 -> 202304 B
#define G1_SMEM_BYTES  (G1_SMEM_FLOATS * 4)

__device__ __forceinline__ void ffma2(unsigned long long& d,
                                      unsigned long long a,
                                      unsigned long long b) {
    asm("fma.rn.f32x2 %0, %1, %2, %0;" : "+l"(d) : "l"(a), "l"(b));
}
__device__ __forceinline__ void cp_async16(unsigned dst, const float* src) {
    asm volatile("cp.async.cg.shared.global [%0], [%1], 16;" :: "r"(dst), "l"(src));
}
__device__ __forceinline__ void cp_commit() {
    asm volatile("cp.async.commit_group;");
}
__device__ __forceinline__ void cp_wait1() {
    asm volatile("cp.async.wait_group 1;");
}

__global__ void __launch_bounds__(G1_BLOCK, 1)
k_gemm1(const float* __restrict__ x, const float* __restrict__ W1) {
    extern __shared__ float sm[];
    float* ws = sm;                       // [1433 * 16]
    float* xs = sm + WS_FLOATS;           // [3][768 * 12]

    const int tid = threadIdx.x;
    const int m0  = blockIdx.x * G1_MT;

    // load W1 into smem (verbatim; k tiles only touch rows < 1432, epi row 1432)
    {
        const float4* W4  = (const float4*)W1;
        float4*       ws4 = (float4*)ws;
        for (int i = tid; i < WS_FLOATS / 4; i += G1_BLOCK) ws4[i] = W4[i];
    }

    // aligned source pointers: one per row this thread copies (rows tid+256s)
    const float* srcp[3];
#pragma unroll
    for (int s = 0; s < 3; s++) {
        int rowg = m0 + tid + 256 * s;
        if (rowg > N_NODES - 1) rowg = N_NODES - 1;   // clamp: garbage masked later
        srcp[s] = x + (size_t)rowg * K_IN - (rowg & 3);  // 16B aligned base
    }
    const unsigned xs_u32 = (unsigned)__cvta_generic_to_shared(xs);
    const unsigned dstbase = xs_u32 + (unsigned)tid * (SROW * 4);

    unsigned long long acc2[3][8];
#pragma unroll
    for (int r = 0; r < 3; r++)
#pragma unroll
        for (int c = 0; c < 8; c++) acc2[r][c] = 0ull;

    __syncthreads();   // ws visible before first compute

    // prologue: issue tiles 0, 1
#pragma unroll
    for (int t = 0; t < 2; t++) {
        unsigned dstg = dstbase + (unsigned)(t * STAGE_F) * 4u;
#pragma unroll
        for (int s = 0; s < 3; s++) {
            unsigned d = dstg + (unsigned)s * (256u * SROW * 4u);
            const float* sp = srcp[s] + 8 * t;
            cp_async16(d,       sp);
            cp_async16(d + 16u, sp + 4);
            cp_async16(d + 32u, sp + 8);
        }
        cp_commit();
    }

    const int xoff = tid * SROW + (tid & 3);
    int st = 0;          // stage of tile t
    int sti = 2;         // stage of tile t+2

    for (int t = 0; t < G1_NT; t++) {
        cp_wait1();          // tile t landed (t+1 may still be in flight)
        __syncthreads();     // all warps done with stage sti's previous tile

        if (t + 2 < G1_NT) {
            unsigned dstg = dstbase + (unsigned)(sti * STAGE_F) * 4u;
#pragma unroll
            for (int s = 0; s < 3; s++) {
                unsigned d = dstg + (unsigned)s * (256u * SROW * 4u);
                const float* sp = srcp[s] + 8 * (t + 2);
                cp_async16(d,       sp);
                cp_async16(d + 16u, sp + 4);
                cp_async16(d + 32u, sp + 8);
            }
        }
        cp_commit();

        const float* xb = xs + st * STAGE_F;
        const float* wr = ws + t * (8 * C1);
#pragma unroll
        for (int k = 0; k < 8; k++) {
            const ulonglong2* wrow = (const ulonglong2*)(wr + k * C1);
            ulonglong2 wa = wrow[0], wb = wrow[1], wc = wrow[2], wd = wrow[3];
#pragma unroll
            for (int r = 0; r < 3; r++) {
                float xv = xb[xoff + r * (256 * SROW) + k];
                unsigned long long xv2;
                asm("mov.b64 %0, {%1, %1};" : "=l"(xv2) : "f"(xv));
                ffma2(acc2[r][0], xv2, wa.x);
                ffma2(acc2[r][1], xv2, wa.y);
                ffma2(acc2[r][2], xv2, wb.x);
                ffma2(acc2[r][3], xv2, wb.y);
                ffma2(acc2[r][4], xv2, wc.x);
                ffma2(acc2[r][5], xv2, wc.y);
                ffma2(acc2[r][6], xv2, wd.x);
                ffma2(acc2[r][7], xv2, wd.y);
            }
        }

        st  = (st  == 2) ? 0 : st + 1;
        sti = (sti == 2) ? 0 : sti + 1;
    }

    // epilogue: k = 1432 (one column, direct LDG — once, negligible)
    {
        const ulonglong2* wrow = (const ulonglong2*)(ws + 1432 * C1);
        ulonglong2 wa = wrow[0], wb = wrow[1], wc = wrow[2], wd = wrow[3];
#pragma unroll
        for (int r = 0; r < 3; r++) {
            int m = m0 + r * 256 + tid;
            if (m > N_NODES - 1) m = N_NODES - 1;
            unsigned long long xv2;
            float xv = __ldg(x + (size_t)m * K_IN + 1432);
            asm("mov.b64 %0, {%1, %1};" : "=l"(xv2) : "f"(xv));
            ffma2(acc2[r][0], xv2, wa.x);
            ffma2(acc2[r][1], xv2, wa.y);
            ffma2(acc2[r][2], xv2, wb.x);
            ffma2(acc2[r][3], xv2, wb.y);
            ffma2(acc2[r][4], xv2, wc.x);
            ffma2(acc2[r][5], xv2, wc.y);
            ffma2(acc2[r][6], xv2, wd.x);
            ffma2(acc2[r][7], xv2, wd.y);
        }
    }

#pragma unroll
    for (int r = 0; r < 3; r++) {
        int m = m0 + r * 256 + tid;
        if (m < N_NODES) {
            float4* o = (float4*)(g_h1 + (size_t)m * 16);
#pragma unroll
            for (int p = 0; p < 4; p++) {
                float2 f0, f1;
                asm("mov.b64 {%0, %1}, %2;" : "=f"(f0.x), "=f"(f0.y) : "l"(acc2[r][2 * p]));
                asm("mov.b64 {%0, %1}, %2;" : "=f"(f1.x), "=f"(f1.y) : "l"(acc2[r][2 * p + 1]));
                o[p] = make_float4(f0.x, f0.y, f1.x, f1.y);
            }
        }
    }
}

// -------- aggregation 1 + bias + relu + GEMM2 fused: ONE WARP PER NODE -------
__global__ void __launch_bounds__(256)
k_agg1(const float* __restrict__ b1, const float* __restrict__ W2) {
    __shared__ float w2s[16 * 7];
    if (threadIdx.x < 16 * 7) w2s[threadIdx.x] = W2[threadIdx.x];
    __syncthreads();

    int g = (blockIdx.x * blockDim.x + threadIdx.x) >> 5;   // node == warp
    if (g >= N_NODES) return;
    int lane = threadIdx.x & 31;
    int e = lane >> 2, q = lane & 3;

    int s = g_off[g];
    int deg = g_off[g + 1] - s;
    const int* cols = g_ecol + s;

    float4 acc = make_float4(0.f, 0.f, 0.f, 0.f);
    for (int i = e; i < deg; i += 8) {
        int c = __ldg(cols + i);
        float dw = g_dinv[c];
        float4 hv = *(const float4*)(g_h1 + (size_t)c * 16 + q * 4);
        acc.x += hv.x * dw; acc.y += hv.y * dw;
        acc.z += hv.z * dw; acc.w += hv.w * dw;
    }

#pragma unroll
    for (int o = 16; o >= 4; o >>= 1) {
        acc.x += __shfl_xor_sync(0xffffffffu, acc.x, o);
        acc.y += __shfl_xor_sync(0xffffffffu, acc.y, o);
        acc.z += __shfl_xor_sync(0xffffffffu, acc.z, o);
        acc.w += __shfl_xor_sync(0xffffffffu, acc.w, o);
    }

    float di = g_dinv[g];
    float4 self = *(const float4*)(g_h1 + (size_t)g * 16 + q * 4);
    float4 bb   = ((const float4*)b1)[q];
    float v0 = fmaxf(bb.x + di * (acc.x + di * self.x), 0.f);
    float v1 = fmaxf(bb.y + di * (acc.y + di * self.y), 0.f);
    float v2 = fmaxf(bb.z + di * (acc.z + di * self.z), 0.f);
    float v3 = fmaxf(bb.w + di * (acc.w + di * self.w), 0.f);

    float h2a[7];
    const float* w2r = w2s + (4 * q) * 7;
#pragma unroll
    for (int c2 = 0; c2 < 7; c2++)
        h2a[c2] = v0 * w2r[c2] + v1 * w2r[7 + c2] + v2 * w2r[14 + c2] + v3 * w2r[21 + c2];
#pragma unroll
    for (int o = 1; o <= 2; o <<= 1)
#pragma unroll
        for (int c2 = 0; c2 < 7; c2++)
            h2a[c2] += __shfl_xor_sync(0xffffffffu, h2a[c2], o);

    if (lane == 0) {
        float4* o4 = (float4*)(g_h2 + (size_t)g * 8);
        o4[0] = make_float4(h2a[0], h2a[1], h2a[2], h2a[3]);
        o4[1] = make_float4(h2a[4], h2a[5], h2a[6], 0.f);
    }
}

// -------- aggregation 2 + bias + log_softmax: ONE WARP PER NODE --------------
__global__ void __launch_bounds__(256)
k_agg2(const float* __restrict__ b2, float* __restrict__ out) {
    int g = (blockIdx.x * blockDim.x + threadIdx.x) >> 5;
    if (g >= N_NODES) return;
    int lane = threadIdx.x & 31;
    int e = lane >> 2, q = lane & 3;

    int s = g_off[g];
    int deg = g_off[g + 1] - s;
    const int* cols = g_ecol + s;

    float a0 = 0.f, a1 = 0.f;
    for (int i = e; i < deg; i += 8) {
        int c = __ldg(cols + i);
        float dw = g_dinv[c];
        float2 hv = *(const float2*)(g_h2 + (size_t)c * 8 + q * 2);
        a0 += hv.x * dw;
        a1 += hv.y * dw;
    }
#pragma unroll
    for (int o = 16; o >= 4; o >>= 1) {
        a0 += __shfl_xor_sync(0xffffffffu, a0, o);
        a1 += __shfl_xor_sync(0xffffffffu, a1, o);
    }

    float di = g_dinv[g];
    float dd = di * di;
    float2 self = *(const float2*)(g_h2 + (size_t)g * 8 + q * 2);
    float bb0 = b2[2 * q];
    float bb1 = (q < 3) ? b2[2 * q + 1] : 0.f;
    a0 = bb0 + di * a0 + dd * self.x;
    a1 = bb1 + di * a1 + dd * self.y;

    float m = (q == 3) ? a0 : fmaxf(a0, a1);
    m = fmaxf(m, __shfl_xor_sync(0xffffffffu, m, 1, 4));
    m = fmaxf(m, __shfl_xor_sync(0xffffffffu, m, 2, 4));
    float e0 = expf(a0 - m);
    float e1 = (q == 3) ? 0.f : expf(a1 - m);
    float ss = e0 + e1;
    ss += __shfl_xor_sync(0xffffffffu, ss, 1, 4);
    ss += __shfl_xor_sync(0xffffffffu, ss, 2, 4);
    float ls = m + logf(ss);

    if (e == 0) {
        out[(size_t)g * 7 + 2 * q] = a0 - ls;
        if (q < 3) out[(size_t)g * 7 + 2 * q + 1] = a1 - ls;
    }
}

// ---------------- launch ------------------------------------------------------
static cudaStream_t s_csr = 0;
static cudaEvent_t  ev_fork = 0, ev_join = 0;

extern "C" void kernel_launch(void* const* d_in, const int* in_sizes, int n_in,
                              void* d_out, int out_size) {
    const float* x   = (const float*)d_in[0];
    const int*   row = (const int*)  d_in[1];
    const int*   col = (const int*)  d_in[2];
    const float* W1  = (const float*)d_in[3];
    const float* b1  = (const float*)d_in[4];
    const float* W2  = (const float*)d_in[5];
    const float* b2  = (const float*)d_in[6];
    float* out = (float*)d_out;

    if (!s_csr) {
        cudaStreamCreateWithFlags(&s_csr, cudaStreamNonBlocking);
        cudaEventCreateWithFlags(&ev_fork, cudaEventDisableTiming);
        cudaEventCreateWithFlags(&ev_join, cudaEventDisableTiming);
        cudaFuncSetAttribute(k_gemm1, cudaFuncAttributeMaxDynamicSharedMemorySize,
                             G1_SMEM_BYTES);
    }

    // fork: CSR chain onto side stream (overlaps with GEMM1)
    cudaEventRecord(ev_fork, 0);
    cudaStreamWaitEvent(s_csr, ev_fork, 0);

    k_zero_cnt<<<(N_NODES / 4 + 255) / 256, 256, 0, s_csr>>>();
    k_count   <<<(N_EDGES / 8 + 255) / 256, 256, 0, s_csr>>>(row);
    k_scan    <<<1, 1024, 0, s_csr>>>();

    // main stream: GEMM1
    k_gemm1<<<G1_GRID, G1_BLOCK, G1_SMEM_BYTES>>>(x, W1);

    k_place<<<(N_EDGES / 8 + 255) / 256, 256, 0, s_csr>>>(row, col);

    // join: aggregation needs both CSR and h1
    cudaEventRecord(ev_join, s_csr);
    cudaStreamWaitEvent(0, ev_join, 0);

    k_agg1<<<(N_NODES * 32 + 255) / 256, 256>>>(b1, W2);
    k_agg2<<<(N_NODES * 32 + 255) / 256, 256>>>(b2, out);
}

// round 12
// speedup vs baseline: 1.0444x; 1.0444x over previous
#include <cuda_runtime.h>
#include <math.h>
#include <stdint.h>

#define N_NODES 100000
#define N_EDGES 3200000
#define K_IN    1433
#define C1      16
#define NTOT_F  143300000u

// ---------------- scratch (static device globals; no allocation) ------------
__device__ __align__(16) int   g_cnt[N_NODES];
__device__ __align__(16) int   g_off[N_NODES + 4];
__device__ __align__(16) int   g_pos[N_NODES];
__device__ __align__(16) float g_dinv[N_NODES];
__device__ __align__(16) int   g_ecol[N_EDGES];
__device__ __align__(16) float g_h1[N_NODES * 16];
__device__ __align__(16) float g_h2[N_NODES * 8];

// ---------------- degree / CSR build ---------------------------------------
__global__ void k_zero_cnt() {
    int i = blockIdx.x * blockDim.x + threadIdx.x;
    if (i * 4 < N_NODES) ((int4*)g_cnt)[i] = make_int4(0, 0, 0, 0);
}

__global__ void k_count(const int* __restrict__ row) {
    int i = blockIdx.x * blockDim.x + threadIdx.x;
    if (i * 8 >= N_EDGES) return;
    int4 r0 = ((const int4*)row)[2 * i];
    int4 r1 = ((const int4*)row)[2 * i + 1];
    atomicAdd(&g_cnt[r0.x], 1);
    atomicAdd(&g_cnt[r0.y], 1);
    atomicAdd(&g_cnt[r0.z], 1);
    atomicAdd(&g_cnt[r0.w], 1);
    atomicAdd(&g_cnt[r1.x], 1);
    atomicAdd(&g_cnt[r1.y], 1);
    atomicAdd(&g_cnt[r1.z], 1);
    atomicAdd(&g_cnt[r1.w], 1);
}

__global__ void k_scan() {
    const int T = 1024, ACT = 1000, CH4 = 25;
    int t = threadIdx.x;
    __shared__ int ps[T];
    int sum = 0;
    if (t < ACT) {
        const int4* c4 = (const int4*)g_cnt + t * CH4;
#pragma unroll
        for (int i = 0; i < CH4; i++) { int4 v = c4[i]; sum += v.x + v.y + v.z + v.w; }
    }
    ps[t] = sum;
    __syncthreads();
    for (int off = 1; off < T; off <<= 1) {
        int v = (t >= off) ? ps[t - off] : 0;
        __syncthreads();
        ps[t] += v;
        __syncthreads();
    }
    if (t < ACT) {
        int run = (t > 0) ? ps[t - 1] : 0;
        const int4* c4 = (const int4*)g_cnt + t * CH4;
        int4*   o4 = (int4*)g_off + t * CH4;
        int4*   p4 = (int4*)g_pos + t * CH4;
        float4* d4 = (float4*)g_dinv + t * CH4;
#pragma unroll 5
        for (int i = 0; i < CH4; i++) {
            int4 v = c4[i];
            int4 o;
            o.x = run; o.y = o.x + v.x; o.z = o.y + v.y; o.w = o.z + v.z;
            run = o.w + v.w;
            o4[i] = o; p4[i] = o;
            float4 dv;
            dv.x = rsqrtf((float)(v.x + 1)); dv.y = rsqrtf((float)(v.y + 1));
            dv.z = rsqrtf((float)(v.z + 1)); dv.w = rsqrtf((float)(v.w + 1));
            d4[i] = dv;
        }
        if (t == ACT - 1) g_off[N_NODES] = run;
    }
}

__global__ void k_place(const int* __restrict__ row, const int* __restrict__ col) {
    int i = blockIdx.x * blockDim.x + threadIdx.x;
    if (i * 8 >= N_EDGES) return;
    int4 r0 = ((const int4*)row)[2 * i];
    int4 r1 = ((const int4*)row)[2 * i + 1];
    int4 c0 = ((const int4*)col)[2 * i];
    int4 c1 = ((const int4*)col)[2 * i + 1];
    int p0 = atomicAdd(&g_pos[r0.x], 1);
    int p1 = atomicAdd(&g_pos[r0.y], 1);
    int p2 = atomicAdd(&g_pos[r0.z], 1);
    int p3 = atomicAdd(&g_pos[r0.w], 1);
    int p4 = atomicAdd(&g_pos[r1.x], 1);
    int p5 = atomicAdd(&g_pos[r1.y], 1);
    int p6 = atomicAdd(&g_pos[r1.z], 1);
    int p7 = atomicAdd(&g_pos[r1.w], 1);
    g_ecol[p0] = c0.x;
    g_ecol[p1] = c0.y;
    g_ecol[p2] = c0.z;
    g_ecol[p3] = c0.w;
    g_ecol[p4] = c1.x;
    g_ecol[p5] = c1.y;
    g_ecol[p6] = c1.z;
    g_ecol[p7] = c1.w;
}

// ---------------- GEMM1: 32-k chunks, 16B cp.async, W streamed ---------------
// Chunk c covers k in [32c, 32c+32) (c=44: 25 valid). Per row, 9 x 16B copies
// starting at the row's 16B-aligned base (per-row shift o = row&3, <=12B slop).
// Staging slot base (bytes) = slot*144 + (slot>>3)*16 -> cp stays 16B-aligned
// AND the compute LDS pattern (4*slot + 4*(slot>>3) + slot&3 mod 32) hits all
// 32 banks exactly once per warp (enumerated) -> conflict-free.
// W1 is NOT resident: 2KB per-chunk slices double-buffered via cp.async (L2).
#define G1_BLOCK  352
#define G1_MT     704
#define G1_GRID   143                 // 143*704 = 100672 >= 100000, one wave
#define NCH       45                  // 44 full 32-k chunks + 25-k tail
#define STG_B     102768              // bytes per x stage (slot 703 end)
#define WOFF_B    (2 * STG_B)         // 205536
#define G1_SMEM_BYTES (WOFF_B + 2 * 2048 + 64)   // 209,696 B

__device__ __forceinline__ void ffma2(unsigned long long& d,
                                      unsigned long long a,
                                      unsigned long long b) {
    asm("fma.rn.f32x2 %0, %1, %2, %0;" : "+l"(d) : "l"(a), "l"(b));
}
__device__ __forceinline__ void cp16(uint32_t dst, const float* src) {
    asm volatile("cp.async.cg.shared.global [%0], [%1], 16;" :: "r"(dst), "l"(src));
}
__device__ __forceinline__ void cp_commit() { asm volatile("cp.async.commit_group;"); }
__device__ __forceinline__ void cp_wait1()  { asm volatile("cp.async.wait_group 1;"); }

__global__ void __launch_bounds__(G1_BLOCK, 1)
k_gemm1(const float* __restrict__ x, const float* __restrict__ W1) {
    extern __shared__ float sm[];
    const int tid = threadIdx.x;
    const int m0  = blockIdx.x * G1_MT;
    const uint32_t smb = (uint32_t)__cvta_generic_to_shared(sm);

    // per-row invariants (rows tid and tid+352)
    const float* srcp[2];
    uint32_t dstb[2];          // smem byte addr of slot base (stage 0)
    uint32_t fbase[2];         // global float index of aligned row base
    int      xoff[2];          // float offset of k=0 within stage
#pragma unroll
    for (int s = 0; s < 2; s++) {
        int slot = tid + 352 * s;
        int gm = m0 + slot;
        if (gm > N_NODES - 1) gm = N_NODES - 1;     // clamp; masked at store
        int o = gm & 3;
        fbase[s] = (uint32_t)gm * (uint32_t)K_IN - (uint32_t)o;
        srcp[s]  = x + fbase[s];
        uint32_t base_b = (uint32_t)slot * 144u + (uint32_t)(slot >> 3) * 16u;
        dstb[s] = smb + base_b;
        xoff[s] = (int)(base_b >> 2) + o;
    }
    const uint32_t wdst = smb + WOFF_B + (uint32_t)tid * 16u;
    const float*   wsrc = W1 + tid * 4;

    unsigned long long acc2[2][8];
#pragma unroll
    for (int s = 0; s < 2; s++)
#pragma unroll
        for (int c = 0; c < 8; c++) acc2[s][c] = 0ull;

    // prologue: issue chunks 0 and 1 (both fully in-bounds; c<44)
#pragma unroll
    for (int c = 0; c < 2; c++) {
#pragma unroll
        for (int s = 0; s < 2; s++) {
            uint32_t d0 = dstb[s] + (uint32_t)(c & 1) * STG_B;
            const float* sp = srcp[s] + 32 * c;
#pragma unroll
            for (int j = 0; j < 9; j++) cp16(d0 + 16u * j, sp + 4 * j);
        }
        if (tid < 128) cp16(wdst + (uint32_t)(c & 1) * 2048u, wsrc + 512 * c);
        cp_commit();
    }

    for (int c = 0; c < NCH; c++) {
        cp_wait1();              // chunk c landed (c+1 may be in flight)
        __syncthreads();

        const float* stgf = sm + (c & 1) * (STG_B / 4);
        const float* wf   = sm + (WOFF_B / 4) + (c & 1) * 512;

        if (c != 44) {
#pragma unroll
            for (int k = 0; k < 32; k++) {
                const ulonglong2* wr = (const ulonglong2*)(wf + k * 16);
                ulonglong2 wa = wr[0], wb = wr[1], wc = wr[2], wd = wr[3];
#pragma unroll
                for (int s = 0; s < 2; s++) {
                    float xv = stgf[xoff[s] + k];
                    unsigned long long xv2;
                    asm("mov.b64 %0, {%1, %1};" : "=l"(xv2) : "f"(xv));
                    ffma2(acc2[s][0], xv2, wa.x);
                    ffma2(acc2[s][1], xv2, wa.y);
                    ffma2(acc2[s][2], xv2, wb.x);
                    ffma2(acc2[s][3], xv2, wb.y);
                    ffma2(acc2[s][4], xv2, wc.x);
                    ffma2(acc2[s][5], xv2, wc.y);
                    ffma2(acc2[s][6], xv2, wd.x);
                    ffma2(acc2[s][7], xv2, wd.y);
                }
            }
        } else {
            for (int k = 0; k < 25; k++) {           // tail chunk: 25 valid k
                const ulonglong2* wr = (const ulonglong2*)(wf + k * 16);
                ulonglong2 wa = wr[0], wb = wr[1], wc = wr[2], wd = wr[3];
#pragma unroll
                for (int s = 0; s < 2; s++) {
                    float xv = stgf[xoff[s] + k];
                    unsigned long long xv2;
                    asm("mov.b64 %0, {%1, %1};" : "=l"(xv2) : "f"(xv));
                    ffma2(acc2[s][0], xv2, wa.x);
                    ffma2(acc2[s][1], xv2, wa.y);
                    ffma2(acc2[s][2], xv2, wb.x);
                    ffma2(acc2[s][3], xv2, wb.y);
                    ffma2(acc2[s][4], xv2, wc.x);
                    ffma2(acc2[s][5], xv2, wc.y);
                    ffma2(acc2[s][6], xv2, wd.x);
                    ffma2(acc2[s][7], xv2, wd.y);
                }
            }
        }
        __syncthreads();         // everyone done reading stage (c&1)

        int tn = c + 2;
        if (tn < NCH) {
            if (tn != 44) {
#pragma unroll
                for (int s = 0; s < 2; s++) {
                    uint32_t d0 = dstb[s] + (uint32_t)(tn & 1) * STG_B;
                    const float* sp = srcp[s] + 32 * tn;
#pragma unroll
                    for (int j = 0; j < 9; j++) cp16(d0 + 16u * j, sp + 4 * j);
                }
                if (tid < 128) cp16(wdst + (uint32_t)(tn & 1) * 2048u, wsrc + 512 * tn);
            } else {
                // tail chunk: guard x ops at the end of the tensor; W 100 ops
#pragma unroll
                for (int s = 0; s < 2; s++) {
                    uint32_t d0 = dstb[s] + (uint32_t)(tn & 1) * STG_B;
                    const float* sp = srcp[s] + 32 * 44;
#pragma unroll
                    for (int j = 0; j < 9; j++) {
                        uint32_t gf = fbase[s] + 32u * 44u + 4u * j;
                        if (gf + 4u <= NTOT_F) cp16(d0 + 16u * j, sp + 4 * j);
                    }
                }
                if (tid < 100) cp16(wdst + (uint32_t)(tn & 1) * 2048u, wsrc + 512 * 44);
            }
        }
        cp_commit();             // one group per iteration (possibly empty)
    }

    // store h1
#pragma unroll
    for (int s = 0; s < 2; s++) {
        int m = m0 + tid + 352 * s;
        if (m < N_NODES) {
            float4* o4 = (float4*)(g_h1 + (size_t)m * 16);
#pragma unroll
            for (int p = 0; p < 4; p++) {
                float2 f0, f1;
                asm("mov.b64 {%0, %1}, %2;" : "=f"(f0.x), "=f"(f0.y) : "l"(acc2[s][2 * p]));
                asm("mov.b64 {%0, %1}, %2;" : "=f"(f1.x), "=f"(f1.y) : "l"(acc2[s][2 * p + 1]));
                o4[p] = make_float4(f0.x, f0.y, f1.x, f1.y);
            }
        }
    }
}

// -------- aggregation 1 + bias + relu + GEMM2 fused: ONE WARP PER NODE -------
__global__ void __launch_bounds__(256)
k_agg1(const float* __restrict__ b1, const float* __restrict__ W2) {
    __shared__ float w2s[16 * 7];
    if (threadIdx.x < 16 * 7) w2s[threadIdx.x] = W2[threadIdx.x];
    __syncthreads();

    int g = (blockIdx.x * blockDim.x + threadIdx.x) >> 5;
    if (g >= N_NODES) return;
    int lane = threadIdx.x & 31;
    int e = lane >> 2, q = lane & 3;

    int s = g_off[g];
    int deg = g_off[g + 1] - s;
    const int* cols = g_ecol + s;

    float4 acc = make_float4(0.f, 0.f, 0.f, 0.f);
    for (int i = e; i < deg; i += 8) {
        int c = __ldg(cols + i);
        float dw = g_dinv[c];
        float4 hv = *(const float4*)(g_h1 + (size_t)c * 16 + q * 4);
        acc.x += hv.x * dw; acc.y += hv.y * dw;
        acc.z += hv.z * dw; acc.w += hv.w * dw;
    }

#pragma unroll
    for (int o = 16; o >= 4; o >>= 1) {
        acc.x += __shfl_xor_sync(0xffffffffu, acc.x, o);
        acc.y += __shfl_xor_sync(0xffffffffu, acc.y, o);
        acc.z += __shfl_xor_sync(0xffffffffu, acc.z, o);
        acc.w += __shfl_xor_sync(0xffffffffu, acc.w, o);
    }

    float di = g_dinv[g];
    float4 self = *(const float4*)(g_h1 + (size_t)g * 16 + q * 4);
    float4 bb   = ((const float4*)b1)[q];
    float v0 = fmaxf(bb.x + di * (acc.x + di * self.x), 0.f);
    float v1 = fmaxf(bb.y + di * (acc.y + di * self.y), 0.f);
    float v2 = fmaxf(bb.z + di * (acc.z + di * self.z), 0.f);
    float v3 = fmaxf(bb.w + di * (acc.w + di * self.w), 0.f);

    float h2a[7];
    const float* w2r = w2s + (4 * q) * 7;
#pragma unroll
    for (int c2 = 0; c2 < 7; c2++)
        h2a[c2] = v0 * w2r[c2] + v1 * w2r[7 + c2] + v2 * w2r[14 + c2] + v3 * w2r[21 + c2];
#pragma unroll
    for (int o = 1; o <= 2; o <<= 1)
#pragma unroll
        for (int c2 = 0; c2 < 7; c2++)
            h2a[c2] += __shfl_xor_sync(0xffffffffu, h2a[c2], o);

    if (lane == 0) {
        float4* o4 = (float4*)(g_h2 + (size_t)g * 8);
        o4[0] = make_float4(h2a[0], h2a[1], h2a[2], h2a[3]);
        o4[1] = make_float4(h2a[4], h2a[5], h2a[6], 0.f);
    }
}

// -------- aggregation 2 + bias + log_softmax: ONE WARP PER NODE --------------
__global__ void __launch_bounds__(256)
k_agg2(const float* __restrict__ b2, float* __restrict__ out) {
    int g = (blockIdx.x * blockDim.x + threadIdx.x) >> 5;
    if (g >= N_NODES) return;
    int lane = threadIdx.x & 31;
    int e = lane >> 2, q = lane & 3;

    int s = g_off[g];
    int deg = g_off[g + 1] - s;
    const int* cols = g_ecol + s;

    float a0 = 0.f, a1 = 0.f;
    for (int i = e; i < deg; i += 8) {
        int c = __ldg(cols + i);
        float dw = g_dinv[c];
        float2 hv = *(const float2*)(g_h2 + (size_t)c * 8 + q * 2);
        a0 += hv.x * dw;
        a1 += hv.y * dw;
    }
#pragma unroll
    for (int o = 16; o >= 4; o >>= 1) {
        a0 += __shfl_xor_sync(0xffffffffu, a0, o);
        a1 += __shfl_xor_sync(0xffffffffu, a1, o);
    }

    float di = g_dinv[g];
    float dd = di * di;
    float2 self = *(const float2*)(g_h2 + (size_t)g * 8 + q * 2);
    float bb0 = b2[2 * q];
    float bb1 = (q < 3) ? b2[2 * q + 1] : 0.f;
    a0 = bb0 + di * a0 + dd * self.x;
    a1 = bb1 + di * a1 + dd * self.y;

    float m = (q == 3) ? a0 : fmaxf(a0, a1);
    m = fmaxf(m, __shfl_xor_sync(0xffffffffu, m, 1, 4));
    m = fmaxf(m, __shfl_xor_sync(0xffffffffu, m, 2, 4));
    float e0 = expf(a0 - m);
    float e1 = (q == 3) ? 0.f : expf(a1 - m);
    float ss = e0 + e1;
    ss += __shfl_xor_sync(0xffffffffu, ss, 1, 4);
    ss += __shfl_xor_sync(0xffffffffu, ss, 2, 4);
    float ls = m + logf(ss);

    if (e == 0) {
        out[(size_t)g * 7 + 2 * q] = a0 - ls;
        if (q < 3) out[(size_t)g * 7 + 2 * q + 1] = a1 - ls;
    }
}

// ---------------- launch ------------------------------------------------------
static cudaStream_t s_csr = 0;
static cudaEvent_t  ev_fork = 0, ev_join = 0;

extern "C" void kernel_launch(void* const* d_in, const int* in_sizes, int n_in,
                              void* d_out, int out_size) {
    const float* x   = (const float*)d_in[0];
    const int*   row = (const int*)  d_in[1];
    const int*   col = (const int*)  d_in[2];
    const float* W1  = (const float*)d_in[3];
    const float* b1  = (const float*)d_in[4];
    const float* W2  = (const float*)d_in[5];
    const float* b2  = (const float*)d_in[6];
    float* out = (float*)d_out;

    if (!s_csr) {
        cudaStreamCreateWithFlags(&s_csr, cudaStreamNonBlocking);
        cudaEventCreateWithFlags(&ev_fork, cudaEventDisableTiming);
        cudaEventCreateWithFlags(&ev_join, cudaEventDisableTiming);
        cudaFuncSetAttribute(k_gemm1, cudaFuncAttributeMaxDynamicSharedMemorySize,
                             G1_SMEM_BYTES);
    }

    // fork: CSR chain onto side stream (overlaps with GEMM1)
    cudaEventRecord(ev_fork, 0);
    cudaStreamWaitEvent(s_csr, ev_fork, 0);

    k_zero_cnt<<<(N_NODES / 4 + 255) / 256, 256, 0, s_csr>>>();
    k_count   <<<(N_EDGES / 8 + 255) / 256, 256, 0, s_csr>>>(row);
    k_scan    <<<1, 1024, 0, s_csr>>>();

    // main stream: GEMM1 (4th submission -> profiled slot)
    k_gemm1<<<G1_GRID, G1_BLOCK, G1_SMEM_BYTES>>>(x, W1);

    k_place<<<(N_EDGES / 8 + 255) / 256, 256, 0, s_csr>>>(row, col);

    // join: aggregation needs both CSR and h1
    cudaEventRecord(ev_join, s_csr);
    cudaStreamWaitEvent(0, ev_join, 0);

    k_agg1<<<(N_NODES * 32 + 255) / 256, 256>>>(b1, W2);
    k_agg2<<<(N_NODES * 32 + 255) / 256, 256>>>(b2, out);
}